// round 15
// baseline (speedup 1.0000x reference)
#include <cuda_runtime.h>
#include <cuda_bf16.h>
#include <cstdint>
#include <math.h>

typedef unsigned int u32;

#define D 128
#define HID 64

// Per-node projections in bf16: P[i][0:64] = embeds[i] @ W1[0:128,:]
//                               P[i][64:128] = embeds[i] @ W1[128:256,:]
__device__ __nv_bfloat16 g_Pb[(size_t)50000 * 2 * HID];
// Constant part: embeds[n] @ W1[256:384,:] + b1  (bf16x2 mirror)
__device__ __align__(16) __nv_bfloat162 g_cvec_bf[HID / 2];
// W2 in bf16x2 (precomputed by cvec block)
__device__ __align__(16) __nv_bfloat162 g_w2_bf[HID / 2];

// ---------------------------------------------------------------------------
// cp.async helpers
// ---------------------------------------------------------------------------
__device__ __forceinline__ void cpa16(u32 saddr, const void* g, int bytes) {
    asm volatile("cp.async.cg.shared.global [%0], [%1], 16, %2;"
                 :: "r"(saddr), "l"(g), "r"(bytes));
}
__device__ __forceinline__ void cpa_commit() {
    asm volatile("cp.async.commit_group;");
}
template <int N>
__device__ __forceinline__ void cpa_wait() {
    asm volatile("cp.async.wait_group %0;" :: "n"(N));
}

// ---------------------------------------------------------------------------
// K1: tensor-core proj. Block 0 computes cvec + W2 mirror (first wave,
// concurrent). Blocks 1..nb: P = embeds @ [W1a | W1b]  (M=n_nodes, N=128, K=128)
// mma.sync.m16n8k8.tf32 (raw fp32 bits). Block tile 128x128, 8 warps (2x4),
// warp tile 64x32. K pipelined in chunks of 16, cp.async double buffer.
// (MTILE=128: B panel staged once per 128 rows — half the L2 restage traffic
//  of the MTILE=64 variant, empirically the faster config.)
// ---------------------------------------------------------------------------
#define MTILE 128
#define KCHUNK 16
#define APITCH 20      // (20g+tg)%32 = 4g+tg distinct -> conflict-free
#define BPITCH 136     // (8tg+g)%32 distinct -> conflict-free

__global__ __launch_bounds__(256) void proj_mma(const float* __restrict__ embeds,
                                                const float* __restrict__ W1,
                                                const float* __restrict__ b1,
                                                const float* __restrict__ W2,
                                                const int* __restrict__ n_ptr,
                                                int n_nodes) {
    __shared__ u32 As[2][MTILE * APITCH];   // 2 x 10.24 KB
    __shared__ u32 Bs[2][KCHUNK * BPITCH];  // 2 x  8.70 KB

    const int tid = threadIdx.x;

    // ---- block 0: cvec + bf16 W2 mirror (first wave, concurrent) ----
    if (blockIdx.x == 0) {
        float* red = (float*)As;
        float* fin = red + 4 * HID;
        int t = tid >> 6;
        int j = tid & 63;
        int n = n_ptr[0];
        const float* e = embeds + (size_t)n * D;
        float acc = 0.f;
#pragma unroll 8
        for (int k = t * 32; k < t * 32 + 32; k++)
            acc = fmaf(e[k], W1[(2 * D + k) * HID + j], acc);
        red[t * HID + j] = acc;
        __syncthreads();
        if (t == 0)
            fin[j] = b1[j] + red[0 * HID + j] + red[1 * HID + j] +
                     red[2 * HID + j] + red[3 * HID + j];
        __syncthreads();
        if (tid < HID / 2) {
            g_cvec_bf[tid] = __floats2bfloat162_rn(fin[2 * tid], fin[2 * tid + 1]);
            g_w2_bf[tid]   = __floats2bfloat162_rn(W2[2 * tid], W2[2 * tid + 1]);
        }
        return;
    }

    const int warpid = tid >> 5;
    const int lane   = tid & 31;
    const int g      = lane >> 2;
    const int tg     = lane & 3;
    const int warp_m = warpid & 1;   // rows warp_m*64
    const int warp_n = warpid >> 1;  // cols warp_n*32
    const int rowBase = (blockIdx.x - 1) * MTILE;

    u32 sAs = (u32)__cvta_generic_to_shared(&As[0][0]);
    u32 sBs = (u32)__cvta_generic_to_shared(&Bs[0][0]);

    // stage one KCHUNK: A = 128x16 (512 float4, 2/thread); B = 16x128 (512 float4, 2/thread)
    auto stage = [&](int buf, int kc) {
#pragma unroll
        for (int i = 0; i < 2; i++) {
            int f  = tid + i * 256;
            int r  = f >> 2;
            int k4 = (f & 3) * 4;
            int gr = rowBase + r;
            int bytes = (gr < n_nodes) ? 16 : 0;
            const float* gp = &embeds[(size_t)(gr < n_nodes ? gr : 0) * D + kc + k4];
            cpa16(sAs + (buf * MTILE * APITCH + r * APITCH + k4) * 4, gp, bytes);
        }
#pragma unroll
        for (int i = 0; i < 2; i++) {
            int f  = tid + i * 256;
            int kk = f >> 5;
            int n4 = (f & 31) * 4;
            int kg = kc + kk;
            const float* gp = (n4 < HID) ? &W1[kg * HID + n4]
                                         : &W1[(D + kg) * HID + (n4 - HID)];
            cpa16(sBs + (buf * KCHUNK * BPITCH + kk * BPITCH + n4) * 4, gp, 16);
        }
        cpa_commit();
    };

    float c[4][4][4];
#pragma unroll
    for (int m = 0; m < 4; m++)
#pragma unroll
        for (int n = 0; n < 4; n++)
#pragma unroll
            for (int r = 0; r < 4; r++) c[m][n][r] = 0.f;

    stage(0, 0);

    const int NITER = D / KCHUNK;   // 8
    for (int it = 0; it < NITER; it++) {
        int buf = it & 1;
        if (it < NITER - 1) stage(buf ^ 1, (it + 1) * KCHUNK);
        if (it < NITER - 1) cpa_wait<1>(); else cpa_wait<0>();
        __syncthreads();

        const u32* A = &As[buf][0];
        const u32* B = &Bs[buf][0];
#pragma unroll
        for (int ks = 0; ks < KCHUNK; ks += 8) {
            u32 a[4][4], b[4][2];
#pragma unroll
            for (int m = 0; m < 4; m++) {
                int r0 = warp_m * 64 + m * 16;
                a[m][0] = A[(r0 + g)     * APITCH + ks + tg];
                a[m][1] = A[(r0 + g + 8) * APITCH + ks + tg];
                a[m][2] = A[(r0 + g)     * APITCH + ks + tg + 4];
                a[m][3] = A[(r0 + g + 8) * APITCH + ks + tg + 4];
            }
#pragma unroll
            for (int n = 0; n < 4; n++) {
                int c0 = warp_n * 32 + n * 8 + g;
                b[n][0] = B[(ks + tg)     * BPITCH + c0];
                b[n][1] = B[(ks + tg + 4) * BPITCH + c0];
            }
#pragma unroll
            for (int m = 0; m < 4; m++)
#pragma unroll
                for (int n = 0; n < 4; n++) {
                    asm volatile(
                        "mma.sync.aligned.m16n8k8.row.col.f32.tf32.tf32.f32 "
                        "{%0,%1,%2,%3}, {%4,%5,%6,%7}, {%8,%9}, {%0,%1,%2,%3};"
                        : "+f"(c[m][n][0]), "+f"(c[m][n][1]),
                          "+f"(c[m][n][2]), "+f"(c[m][n][3])
                        : "r"(a[m][0]), "r"(a[m][1]), "r"(a[m][2]), "r"(a[m][3]),
                          "r"(b[n][0]), "r"(b[n][1]));
                }
        }
        __syncthreads();
    }

    // epilogue: rows g, g+8; cols 2*tg, 2*tg+1 -> bf16
#pragma unroll
    for (int m = 0; m < 4; m++) {
        int r0 = rowBase + warp_m * 64 + m * 16;
#pragma unroll
        for (int n = 0; n < 4; n++) {
            int col = warp_n * 32 + n * 8 + tg * 2;
            int ra = r0 + g, rb = r0 + g + 8;
            if (ra < n_nodes)
                *(__nv_bfloat162*)&g_Pb[(size_t)ra * 128 + col] =
                    __floats2bfloat162_rn(c[m][n][0], c[m][n][1]);
            if (rb < n_nodes)
                *(__nv_bfloat162*)&g_Pb[(size_t)rb * 128 + col] =
                    __floats2bfloat162_rn(c[m][n][2], c[m][n][3]);
        }
    }
}

// ---------------------------------------------------------------------------
// K2: 32 edges per warp, 8 passes of 4 edges (8-lane groups).
// Depth-4 gather ring; per-pass in-loop redistribute (no sw[]/v[] arrays).
// bf16x2 HADD2/HMAX2 + HFMA2 dot; one fast-math tail per warp (32 lanes).
// ---------------------------------------------------------------------------
#define EPW 32

__device__ __forceinline__ __nv_bfloat162 b2of(u32 x) {
    return *reinterpret_cast<__nv_bfloat162*>(&x);
}
__device__ __forceinline__ float blo(__nv_bfloat162 h) {
    u32 x = *reinterpret_cast<u32*>(&h);
    return __uint_as_float(x << 16);
}
__device__ __forceinline__ float bhi(__nv_bfloat162 h) {
    u32 x = *reinterpret_cast<u32*>(&h);
    return __uint_as_float(x & 0xFFFF0000u);
}

__global__ __launch_bounds__(256, 5) void edge_kernel(const float* __restrict__ b2,
                            const float* __restrict__ u,
                            const int* __restrict__ src,
                            const int* __restrict__ dst,
                            float* __restrict__ out,
                            int E) {
    int warp = (int)((blockIdx.x * blockDim.x + threadIdx.x) >> 5);
    int lane = threadIdx.x & 31;
    int q = lane >> 3;          // quarter 0..3
    int l = lane & 7;           // lane within quarter
    int base = warp * EPW;
    if (base >= E) return;

    // hoisted tail inputs (one edge per lane)
    int eTail = base + lane;
    bool tailOn = eTail < E;
    float uv  = tailOn ? __ldg(&u[min(eTail, E - 1)]) : 0.f;
    float b2v = __ldg(&b2[0]);

    // coalesced src/dst for all 32 edges of this warp
    int ecl = min(base + lane, E - 1);
    u32 sAll = (u32)__ldg(&src[ecl]);
    u32 dAll = (u32)__ldg(&dst[ecl]);

    // warp-resident constants: 8 hidden units per lane-in-quarter (bf16x2)
    uint4 cbu = *(const uint4*)&g_cvec_bf[4 * l];
    uint4 wbu = *(const uint4*)&g_w2_bf[4 * l];
    const __nv_bfloat162 z2 = __floats2bfloat162_rn(0.f, 0.f);

    const char* pb = (const char*)g_Pb;   // row i at byte offset i*256

    uint4 pu[4], du[4];                   // depth-4 ring

#define GATHER(p, slot)                                                    \
    {                                                                      \
        u32 s_ = __shfl_sync(0xffffffffu, sAll, (p) * 4 + q);              \
        u32 d_ = __shfl_sync(0xffffffffu, dAll, (p) * 4 + q);              \
        pu[slot] = *(const uint4*)(pb + (s_ << 8) + (l << 4));             \
        du[slot] = *(const uint4*)(pb + (d_ << 8) + 128 + (l << 4));       \
    }

    GATHER(0, 0) GATHER(1, 1) GATHER(2, 2) GATHER(3, 3)

    const int srcl = (lane & 3) * 8;   // source lane for redistribute
    const int sel  = lane >> 2;        // which pass this lane's edge is in
    float sv = 0.f;

#pragma unroll
    for (int p = 0; p < 8; p++) {
        int slot = p & 3;
        __nv_bfloat162 h0 = __hmax2(__hadd2(__hadd2(b2of(pu[slot].x), b2of(du[slot].x)), b2of(cbu.x)), z2);
        __nv_bfloat162 h1 = __hmax2(__hadd2(__hadd2(b2of(pu[slot].y), b2of(du[slot].y)), b2of(cbu.y)), z2);
        __nv_bfloat162 h2 = __hmax2(__hadd2(__hadd2(b2of(pu[slot].z), b2of(du[slot].z)), b2of(cbu.z)), z2);
        __nv_bfloat162 h3 = __hmax2(__hadd2(__hadd2(b2of(pu[slot].w), b2of(du[slot].w)), b2of(cbu.w)), z2);

        // refill this slot with pass p+4's gathers (stays in flight 3 passes)
        if (p + 4 < 8) GATHER(p + 4, slot)

        __nv_bfloat162 acc2 = __hmul2(h0, b2of(wbu.x));
        acc2 = __hfma2(h1, b2of(wbu.y), acc2);
        acc2 = __hfma2(h2, b2of(wbu.z), acc2);
        acc2 = __hfma2(h3, b2of(wbu.w), acc2);
        float acc = blo(acc2) + bhi(acc2);

        acc += __shfl_xor_sync(0xffffffffu, acc, 4);
        acc += __shfl_xor_sync(0xffffffffu, acc, 2);
        acc += __shfl_xor_sync(0xffffffffu, acc, 1);

        // in-loop redistribute: lane j (edge base+j) takes pass p = j>>2's
        // result from lane (j&3)*8
        float t = __shfl_sync(0xffffffffu, acc, srcl);
        if (sel == p) sv = t;
    }
#undef GATHER

    if (tailOn) {
        float swv = sv + b2v;
        float eps = fmaf(-0.9998f, uv, 0.9999f);
        // gate/TEMP = (ln2/5) * (log2(eps) - log2(1-eps))
        float gate5 = 0.13862944f * (__log2f(eps) - __log2f(1.f - eps));
        float z = gate5 + swv * 0.2f;            // TEMP = 5
        out[eTail] = 1.f / (1.f + __expf(-z));
    }
}

// ---------------------------------------------------------------------------
// Inputs (metadata order): embeds, W1, b1, W2, b2, u, src, dst, n
// ---------------------------------------------------------------------------
extern "C" void kernel_launch(void* const* d_in, const int* in_sizes, int n_in,
                              void* d_out, int out_size) {
    const float* embeds = (const float*)d_in[0];
    const float* W1     = (const float*)d_in[1];
    const float* b1     = (const float*)d_in[2];
    const float* W2     = (const float*)d_in[3];
    const float* b2     = (const float*)d_in[4];
    const float* u      = (const float*)d_in[5];
    const int*   src    = (const int*)d_in[6];
    const int*   dst    = (const int*)d_in[7];
    const int*   n_ptr  = (const int*)d_in[8];

    int n_nodes = in_sizes[0] / D;
    int E       = in_sizes[6];

    int nb = (n_nodes + MTILE - 1) / MTILE;
    proj_mma<<<nb + 1, 256>>>(embeds, W1, b1, W2, n_ptr, n_nodes);

    int warps  = (E + EPW - 1) / EPW;
    int blocks = (warps * 32 + 255) / 256;
    edge_kernel<<<blocks, 256>>>(b2, u, src, dst, (float*)d_out, E);
}

// round 16
// speedup vs baseline: 1.0215x; 1.0215x over previous
#include <cuda_runtime.h>
#include <cuda_bf16.h>
#include <cstdint>
#include <math.h>

typedef unsigned int u32;

#define D 128
#define HID 64

// Per-node projections in bf16: P[i][0:64] = embeds[i] @ W1[0:128,:]
//                               P[i][64:128] = embeds[i] @ W1[128:256,:]
__device__ __nv_bfloat16 g_Pb[(size_t)50000 * 2 * HID];
// Constant part: embeds[n] @ W1[256:384,:] + b1  (bf16x2 mirror)
__device__ __align__(16) __nv_bfloat162 g_cvec_bf[HID / 2];
// W2 in bf16x2 (precomputed by cvec block)
__device__ __align__(16) __nv_bfloat162 g_w2_bf[HID / 2];

// ---------------------------------------------------------------------------
// cp.async helpers
// ---------------------------------------------------------------------------
__device__ __forceinline__ void cpa16(u32 saddr, const void* g, int bytes) {
    asm volatile("cp.async.cg.shared.global [%0], [%1], 16, %2;"
                 :: "r"(saddr), "l"(g), "r"(bytes));
}
__device__ __forceinline__ void cpa_commit() {
    asm volatile("cp.async.commit_group;");
}
template <int N>
__device__ __forceinline__ void cpa_wait() {
    asm volatile("cp.async.wait_group %0;" :: "n"(N));
}

// ---------------------------------------------------------------------------
// K1: tensor-core proj. Block 0 computes cvec + W2 mirror (first wave,
// concurrent). Blocks 1..nb: P = embeds @ [W1a | W1b].
// mma.sync.m16n8k8.tf32. Block tile 64x128, 8 warps (2m x 4n), warp 32x32.
// KCHUNK=32: only 4 pipeline iterations / 4 syncs per tile (dynamic smem,
// 53.2KB, double buffered).
// ---------------------------------------------------------------------------
#define MTILE 64
#define KCHUNK 32
#define APITCH 36      // (4g+tg)%32 distinct over 32 lanes -> conflict-free
#define BPITCH 136     // (8tg+g)%32 distinct -> conflict-free
#define A_BUF_U32 (MTILE * APITCH)     // 2304
#define B_BUF_U32 (KCHUNK * BPITCH)    // 4352
#define SMEM_U32  (2 * A_BUF_U32 + 2 * B_BUF_U32)   // 13312 u32 = 53248 B

__global__ __launch_bounds__(256) void proj_mma(const float* __restrict__ embeds,
                                                const float* __restrict__ W1,
                                                const float* __restrict__ b1,
                                                const float* __restrict__ W2,
                                                const int* __restrict__ n_ptr,
                                                int n_nodes) {
    extern __shared__ u32 dsm[];
    u32* Asm = dsm;                      // 2 x A_BUF_U32
    u32* Bsm = dsm + 2 * A_BUF_U32;      // 2 x B_BUF_U32

    const int tid = threadIdx.x;

    // ---- block 0: cvec + bf16 W2 mirror (first wave, concurrent) ----
    if (blockIdx.x == 0) {
        float* red = (float*)dsm;
        float* fin = red + 4 * HID;
        int t = tid >> 6;
        int j = tid & 63;
        int n = n_ptr[0];
        const float* e = embeds + (size_t)n * D;
        float acc = 0.f;
#pragma unroll 8
        for (int k = t * 32; k < t * 32 + 32; k++)
            acc = fmaf(e[k], W1[(2 * D + k) * HID + j], acc);
        red[t * HID + j] = acc;
        __syncthreads();
        if (t == 0)
            fin[j] = b1[j] + red[0 * HID + j] + red[1 * HID + j] +
                     red[2 * HID + j] + red[3 * HID + j];
        __syncthreads();
        if (tid < HID / 2) {
            g_cvec_bf[tid] = __floats2bfloat162_rn(fin[2 * tid], fin[2 * tid + 1]);
            g_w2_bf[tid]   = __floats2bfloat162_rn(W2[2 * tid], W2[2 * tid + 1]);
        }
        return;
    }

    const int warpid = tid >> 5;
    const int lane   = tid & 31;
    const int g      = lane >> 2;
    const int tg     = lane & 3;
    const int warp_m = warpid & 1;   // rows warp_m*32
    const int warp_n = warpid >> 1;  // cols warp_n*32
    const int rowBase = (blockIdx.x - 1) * MTILE;

    u32 sAs = (u32)__cvta_generic_to_shared(Asm);
    u32 sBs = (u32)__cvta_generic_to_shared(Bsm);

    // stage one KCHUNK=32: A = 64x32 (512 float4, 2/thread); B = 32x128 (1024 float4, 4/thread)
    auto stage = [&](int buf, int kc) {
#pragma unroll
        for (int i = 0; i < 2; i++) {
            int f  = tid + i * 256;          // 0..511
            int r  = f >> 3;                 // 0..63
            int k4 = (f & 7) * 4;            // 0,4,..,28
            int gr = rowBase + r;
            int bytes = (gr < n_nodes) ? 16 : 0;
            const float* gp = &embeds[(size_t)(gr < n_nodes ? gr : 0) * D + kc + k4];
            cpa16(sAs + (buf * A_BUF_U32 + r * APITCH + k4) * 4, gp, bytes);
        }
#pragma unroll
        for (int i = 0; i < 4; i++) {
            int f  = tid + i * 256;          // 0..1023
            int kk = f >> 5;                 // 0..31
            int n4 = (f & 31) * 4;           // 0,4,..,124
            int kg = kc + kk;
            const float* gp = (n4 < HID) ? &W1[kg * HID + n4]
                                         : &W1[(D + kg) * HID + (n4 - HID)];
            cpa16(sBs + (buf * B_BUF_U32 + kk * BPITCH + n4) * 4, gp, 16);
        }
        cpa_commit();
    };

    float c[2][4][4];
#pragma unroll
    for (int m = 0; m < 2; m++)
#pragma unroll
        for (int n = 0; n < 4; n++)
#pragma unroll
            for (int r = 0; r < 4; r++) c[m][n][r] = 0.f;

    stage(0, 0);

    const int NITER = D / KCHUNK;   // 4
#pragma unroll
    for (int it = 0; it < NITER; it++) {
        int buf = it & 1;
        if (it < NITER - 1) stage(buf ^ 1, (it + 1) * KCHUNK);
        if (it < NITER - 1) cpa_wait<1>(); else cpa_wait<0>();
        __syncthreads();

        const u32* A = &Asm[buf * A_BUF_U32];
        const u32* B = &Bsm[buf * B_BUF_U32];
#pragma unroll
        for (int ks = 0; ks < KCHUNK; ks += 8) {
            u32 a[2][4], b[4][2];
#pragma unroll
            for (int m = 0; m < 2; m++) {
                int r0 = warp_m * 32 + m * 16;
                a[m][0] = A[(r0 + g)     * APITCH + ks + tg];
                a[m][1] = A[(r0 + g + 8) * APITCH + ks + tg];
                a[m][2] = A[(r0 + g)     * APITCH + ks + tg + 4];
                a[m][3] = A[(r0 + g + 8) * APITCH + ks + tg + 4];
            }
#pragma unroll
            for (int n = 0; n < 4; n++) {
                int c0 = warp_n * 32 + n * 8 + g;
                b[n][0] = B[(ks + tg)     * BPITCH + c0];
                b[n][1] = B[(ks + tg + 4) * BPITCH + c0];
            }
#pragma unroll
            for (int m = 0; m < 2; m++)
#pragma unroll
                for (int n = 0; n < 4; n++) {
                    asm volatile(
                        "mma.sync.aligned.m16n8k8.row.col.f32.tf32.tf32.f32 "
                        "{%0,%1,%2,%3}, {%4,%5,%6,%7}, {%8,%9}, {%0,%1,%2,%3};"
                        : "+f"(c[m][n][0]), "+f"(c[m][n][1]),
                          "+f"(c[m][n][2]), "+f"(c[m][n][3])
                        : "r"(a[m][0]), "r"(a[m][1]), "r"(a[m][2]), "r"(a[m][3]),
                          "r"(b[n][0]), "r"(b[n][1]));
                }
        }
        __syncthreads();
    }

    // epilogue: rows g, g+8; cols 2*tg, 2*tg+1 -> bf16
#pragma unroll
    for (int m = 0; m < 2; m++) {
        int r0 = rowBase + warp_m * 32 + m * 16;
#pragma unroll
        for (int n = 0; n < 4; n++) {
            int col = warp_n * 32 + n * 8 + tg * 2;
            int ra = r0 + g, rb = r0 + g + 8;
            if (ra < n_nodes)
                *(__nv_bfloat162*)&g_Pb[(size_t)ra * 128 + col] =
                    __floats2bfloat162_rn(c[m][n][0], c[m][n][1]);
            if (rb < n_nodes)
                *(__nv_bfloat162*)&g_Pb[(size_t)rb * 128 + col] =
                    __floats2bfloat162_rn(c[m][n][2], c[m][n][3]);
        }
    }
}

// ---------------------------------------------------------------------------
// K2: 32 edges per warp, 8 passes of 4 edges (8-lane groups).
// Depth-4 gather ring; per-pass in-loop redistribute.
// bf16x2 HADD2/HMAX2 + HFMA2 dot; one fast-math tail per warp (32 lanes).
// ---------------------------------------------------------------------------
#define EPW 32

__device__ __forceinline__ __nv_bfloat162 b2of(u32 x) {
    return *reinterpret_cast<__nv_bfloat162*>(&x);
}
__device__ __forceinline__ float blo(__nv_bfloat162 h) {
    u32 x = *reinterpret_cast<u32*>(&h);
    return __uint_as_float(x << 16);
}
__device__ __forceinline__ float bhi(__nv_bfloat162 h) {
    u32 x = *reinterpret_cast<u32*>(&h);
    return __uint_as_float(x & 0xFFFF0000u);
}

__global__ __launch_bounds__(256, 5) void edge_kernel(const float* __restrict__ b2,
                            const float* __restrict__ u,
                            const int* __restrict__ src,
                            const int* __restrict__ dst,
                            float* __restrict__ out,
                            int E) {
    int warp = (int)((blockIdx.x * blockDim.x + threadIdx.x) >> 5);
    int lane = threadIdx.x & 31;
    int q = lane >> 3;          // quarter 0..3
    int l = lane & 7;           // lane within quarter
    int base = warp * EPW;
    if (base >= E) return;

    // hoisted tail inputs (one edge per lane)
    int eTail = base + lane;
    bool tailOn = eTail < E;
    float uv  = tailOn ? __ldg(&u[min(eTail, E - 1)]) : 0.f;
    float b2v = __ldg(&b2[0]);

    // coalesced src/dst for all 32 edges of this warp
    int ecl = min(base + lane, E - 1);
    u32 sAll = (u32)__ldg(&src[ecl]);
    u32 dAll = (u32)__ldg(&dst[ecl]);

    // warp-resident constants: 8 hidden units per lane-in-quarter (bf16x2)
    uint4 cbu = *(const uint4*)&g_cvec_bf[4 * l];
    uint4 wbu = *(const uint4*)&g_w2_bf[4 * l];
    const __nv_bfloat162 z2 = __floats2bfloat162_rn(0.f, 0.f);

    const char* pb = (const char*)g_Pb;   // row i at byte offset i*256

    uint4 pu[4], du[4];                   // depth-4 ring

#define GATHER(p, slot)                                                    \
    {                                                                      \
        u32 s_ = __shfl_sync(0xffffffffu, sAll, (p) * 4 + q);              \
        u32 d_ = __shfl_sync(0xffffffffu, dAll, (p) * 4 + q);              \
        pu[slot] = *(const uint4*)(pb + (s_ << 8) + (l << 4));             \
        du[slot] = *(const uint4*)(pb + (d_ << 8) + 128 + (l << 4));       \
    }

    GATHER(0, 0) GATHER(1, 1) GATHER(2, 2) GATHER(3, 3)

    const int srcl = (lane & 3) * 8;   // source lane for redistribute
    const int sel  = lane >> 2;        // which pass this lane's edge is in
    float sv = 0.f;

#pragma unroll
    for (int p = 0; p < 8; p++) {
        int slot = p & 3;
        __nv_bfloat162 h0 = __hmax2(__hadd2(__hadd2(b2of(pu[slot].x), b2of(du[slot].x)), b2of(cbu.x)), z2);
        __nv_bfloat162 h1 = __hmax2(__hadd2(__hadd2(b2of(pu[slot].y), b2of(du[slot].y)), b2of(cbu.y)), z2);
        __nv_bfloat162 h2 = __hmax2(__hadd2(__hadd2(b2of(pu[slot].z), b2of(du[slot].z)), b2of(cbu.z)), z2);
        __nv_bfloat162 h3 = __hmax2(__hadd2(__hadd2(b2of(pu[slot].w), b2of(du[slot].w)), b2of(cbu.w)), z2);

        // refill this slot with pass p+4's gathers (stays in flight 3 passes)
        if (p + 4 < 8) GATHER(p + 4, slot)

        __nv_bfloat162 acc2 = __hmul2(h0, b2of(wbu.x));
        acc2 = __hfma2(h1, b2of(wbu.y), acc2);
        acc2 = __hfma2(h2, b2of(wbu.z), acc2);
        acc2 = __hfma2(h3, b2of(wbu.w), acc2);
        float acc = blo(acc2) + bhi(acc2);

        acc += __shfl_xor_sync(0xffffffffu, acc, 4);
        acc += __shfl_xor_sync(0xffffffffu, acc, 2);
        acc += __shfl_xor_sync(0xffffffffu, acc, 1);

        // in-loop redistribute: lane j (edge base+j) takes pass p = j>>2's
        // result from lane (j&3)*8
        float t = __shfl_sync(0xffffffffu, acc, srcl);
        if (sel == p) sv = t;
    }
#undef GATHER

    if (tailOn) {
        float swv = sv + b2v;
        float eps = fmaf(-0.9998f, uv, 0.9999f);
        // gate/TEMP = (ln2/5) * (log2(eps) - log2(1-eps))
        float gate5 = 0.13862944f * (__log2f(eps) - __log2f(1.f - eps));
        float z = gate5 + swv * 0.2f;            // TEMP = 5
        out[eTail] = 1.f / (1.f + __expf(-z));
    }
}

// ---------------------------------------------------------------------------
// Inputs (metadata order): embeds, W1, b1, W2, b2, u, src, dst, n
// ---------------------------------------------------------------------------
extern "C" void kernel_launch(void* const* d_in, const int* in_sizes, int n_in,
                              void* d_out, int out_size) {
    const float* embeds = (const float*)d_in[0];
    const float* W1     = (const float*)d_in[1];
    const float* b1     = (const float*)d_in[2];
    const float* W2     = (const float*)d_in[3];
    const float* b2     = (const float*)d_in[4];
    const float* u      = (const float*)d_in[5];
    const int*   src    = (const int*)d_in[6];
    const int*   dst    = (const int*)d_in[7];
    const int*   n_ptr  = (const int*)d_in[8];

    int n_nodes = in_sizes[0] / D;
    int E       = in_sizes[6];

    const int smem_bytes = SMEM_U32 * 4;   // 53248
    cudaFuncSetAttribute(proj_mma, cudaFuncAttributeMaxDynamicSharedMemorySize,
                         smem_bytes);

    int nb = (n_nodes + MTILE - 1) / MTILE;
    proj_mma<<<nb + 1, 256, smem_bytes>>>(embeds, W1, b1, W2, n_ptr, n_nodes);

    int warps  = (E + EPW - 1) / EPW;
    int blocks = (warps * 32 + 255) / 256;
    edge_kernel<<<blocks, 256>>>(b2, u, src, dst, (float*)d_out, E);
}